// round 2
// baseline (speedup 1.0000x reference)
#include <cuda_runtime.h>
#include <cuda_bf16.h>

#define NN 100000
#define NE 6400000
static constexpr float BN_EPS = 1e-5f;

// ---------------- scratch (static device arrays; no runtime alloc) ---------
__device__ float4 g_A[NN];            // h @ msg_W1[0:4]   (dst-side partial)
__device__ float4 g_B[NN];            // h @ msg_W1[4:8]+b (src-side partial)
__device__ float4 g_aggr[NN];         // scatter-add target
__device__ float4 g_zu[NN];           // node MLP layer-1 pre-BN
__device__ float4 g_z2u[NN];          // node MLP layer-2 pre-BN

__device__ double   g_sum[4];
__device__ double   g_sq[4];
__device__ unsigned g_cnt;

__device__ float g_ma1[4], g_mb1[4];  // msg BN1 affine (alpha, beta)
__device__ float g_ma2[4], g_mb2[4];  // msg BN2 affine
__device__ float g_ua1[4], g_ub1[4];  // upd BN1 affine
__device__ float g_ua2[4], g_ub2[4];  // upd BN2 affine

struct P {
    const float* pos; const float* vel;
    const int* src; const int* dst;   // edge_index rows (int32 after JAX x64 canonicalization)
    const float *mW1,*mb1,*mg1,*mbe1,*mW2,*mb2,*mg2,*mbe2;
    const float *uW1,*ub1,*ug1,*ube1,*uW2,*ub2,*ug2,*ube2;
    const float *pW,*pb;
    float* out;
};

// ---------------- reduction helpers ----------------------------------------
__device__ __forceinline__ void reduce_stats(float s[4], float q[4]) {
    #pragma unroll
    for (int o = 16; o > 0; o >>= 1) {
        #pragma unroll
        for (int c = 0; c < 4; c++) {
            s[c] += __shfl_down_sync(0xffffffffu, s[c], o);
            q[c] += __shfl_down_sync(0xffffffffu, q[c], o);
        }
    }
    __shared__ float shs[4][8], shq[4][8];
    int w = threadIdx.x >> 5;
    if ((threadIdx.x & 31) == 0) {
        #pragma unroll
        for (int c = 0; c < 4; c++) { shs[c][w] = s[c]; shq[c][w] = q[c]; }
    }
    __syncthreads();
    if (threadIdx.x == 0) {
        int nw = blockDim.x >> 5;
        #pragma unroll
        for (int c = 0; c < 4; c++) {
            double ts = 0.0, tq = 0.0;
            for (int i = 0; i < nw; i++) { ts += (double)shs[c][i]; tq += (double)shq[c][i]; }
            atomicAdd(&g_sum[c], ts);
            atomicAdd(&g_sq[c],  tq);
        }
    }
}

// last block through the counter folds the moments into BN affine params
__device__ __forceinline__ void finalize_bn(double count, const float* gamma, const float* beta,
                                            float* alpha_out, float* beta_out) {
    __threadfence();
    if (threadIdx.x == 0) {
        if (atomicAdd(&g_cnt, 1u) == gridDim.x - 1) {
            #pragma unroll
            for (int c = 0; c < 4; c++) {
                double m = ((volatile double*)g_sum)[c] / count;
                double v = ((volatile double*)g_sq)[c] / count - m * m;
                float  al = __ldg(&gamma[c]) * rsqrtf((float)v + BN_EPS);
                alpha_out[c] = al;
                beta_out[c]  = __ldg(&beta[c]) - (float)m * al;
                g_sum[c] = 0.0; g_sq[c] = 0.0;
            }
            g_cnt = 0u;
            __threadfence();
        }
    }
}

// ---------------- K0: per-node precompute + state reset --------------------
__global__ void k_pre(P p) {
    int n = blockIdx.x * blockDim.x + threadIdx.x;
    if (blockIdx.x == 0 && threadIdx.x == 0) {
        #pragma unroll
        for (int c = 0; c < 4; c++) { g_sum[c] = 0.0; g_sq[c] = 0.0; }
        g_cnt = 0u;
    }
    if (n >= NN) return;
    float h0 = __ldg(&p.pos[2*n]),  h1 = __ldg(&p.pos[2*n+1]);
    float h2 = __ldg(&p.vel[2*n]),  h3 = __ldg(&p.vel[2*n+1]);
    float A[4], B[4];
    #pragma unroll
    for (int c = 0; c < 4; c++) {
        A[c] = h0*__ldg(&p.mW1[ 0+c]) + h1*__ldg(&p.mW1[ 4+c])
             + h2*__ldg(&p.mW1[ 8+c]) + h3*__ldg(&p.mW1[12+c]);
        B[c] = __ldg(&p.mb1[c])
             + h0*__ldg(&p.mW1[16+c]) + h1*__ldg(&p.mW1[20+c])
             + h2*__ldg(&p.mW1[24+c]) + h3*__ldg(&p.mW1[28+c]);
    }
    g_A[n]    = make_float4(A[0], A[1], A[2], A[3]);
    g_B[n]    = make_float4(B[0], B[1], B[2], B[3]);
    g_aggr[n] = make_float4(0.f, 0.f, 0.f, 0.f);
}

// ---------------- K1: edge pass 1 — layer-1 stats ---------------------------
__global__ void k_e1(P p) {
    float s[4] = {0,0,0,0}, q[4] = {0,0,0,0};
    int stride = gridDim.x * blockDim.x;
    for (int i = blockIdx.x * blockDim.x + threadIdx.x; i < NE; i += stride) {
        int si = __ldg(&p.src[i]);
        int di = __ldg(&p.dst[i]);
        float4 A = g_A[di], B = g_B[si];
        float z[4] = {A.x + B.x, A.y + B.y, A.z + B.z, A.w + B.w};
        #pragma unroll
        for (int c = 0; c < 4; c++) { s[c] += z[c]; q[c] += z[c]*z[c]; }
    }
    reduce_stats(s, q);
    finalize_bn((double)NE, p.mg1, p.mbe1, g_ma1, g_mb1);
}

// ---------------- K2: edge pass 2 — layer-2 stats ---------------------------
__global__ void k_e2(P p) {
    float a1[4], b1[4], W2[16], bb2[4];
    #pragma unroll
    for (int c = 0; c < 4; c++) { a1[c] = g_ma1[c]; b1[c] = g_mb1[c]; bb2[c] = __ldg(&p.mb2[c]); }
    #pragma unroll
    for (int k = 0; k < 16; k++) W2[k] = __ldg(&p.mW2[k]);

    float s[4] = {0,0,0,0}, q[4] = {0,0,0,0};
    int stride = gridDim.x * blockDim.x;
    for (int i = blockIdx.x * blockDim.x + threadIdx.x; i < NE; i += stride) {
        int si = __ldg(&p.src[i]);
        int di = __ldg(&p.dst[i]);
        float4 A = g_A[di], B = g_B[si];
        float y[4];
        y[0] = fmaxf(0.f, (A.x + B.x) * a1[0] + b1[0]);
        y[1] = fmaxf(0.f, (A.y + B.y) * a1[1] + b1[1]);
        y[2] = fmaxf(0.f, (A.z + B.z) * a1[2] + b1[2]);
        y[3] = fmaxf(0.f, (A.w + B.w) * a1[3] + b1[3]);
        #pragma unroll
        for (int c = 0; c < 4; c++) {
            float z2 = bb2[c] + y[0]*W2[c] + y[1]*W2[4+c] + y[2]*W2[8+c] + y[3]*W2[12+c];
            s[c] += z2; q[c] += z2*z2;
        }
    }
    reduce_stats(s, q);
    finalize_bn((double)NE, p.mg2, p.mbe2, g_ma2, g_mb2);
}

// ---------------- K3: edge pass 3 — message + scatter-add -------------------
__global__ void k_e3(P p) {
    float a1[4], b1[4], a2[4], b2a[4], W2[16], bb2[4];
    #pragma unroll
    for (int c = 0; c < 4; c++) {
        a1[c] = g_ma1[c]; b1[c] = g_mb1[c];
        a2[c] = g_ma2[c]; b2a[c] = g_mb2[c];
        bb2[c] = __ldg(&p.mb2[c]);
    }
    #pragma unroll
    for (int k = 0; k < 16; k++) W2[k] = __ldg(&p.mW2[k]);

    int stride = gridDim.x * blockDim.x;
    for (int i = blockIdx.x * blockDim.x + threadIdx.x; i < NE; i += stride) {
        int si = __ldg(&p.src[i]);
        int di = __ldg(&p.dst[i]);
        float4 A = g_A[di], B = g_B[si];
        float y[4];
        y[0] = fmaxf(0.f, (A.x + B.x) * a1[0] + b1[0]);
        y[1] = fmaxf(0.f, (A.y + B.y) * a1[1] + b1[1]);
        y[2] = fmaxf(0.f, (A.z + B.z) * a1[2] + b1[2]);
        y[3] = fmaxf(0.f, (A.w + B.w) * a1[3] + b1[3]);
        float m[4];
        #pragma unroll
        for (int c = 0; c < 4; c++) {
            float z2 = bb2[c] + y[0]*W2[c] + y[1]*W2[4+c] + y[2]*W2[8+c] + y[3]*W2[12+c];
            m[c] = fmaxf(0.f, z2 * a2[c] + b2a[c]);
        }
        float4* addr = &g_aggr[di];
        asm volatile("red.global.add.v4.f32 [%0], {%1, %2, %3, %4};"
                     :: "l"(addr), "f"(m[0]), "f"(m[1]), "f"(m[2]), "f"(m[3])
                     : "memory");
    }
}

// ---------------- K4: node update layer-1 stats ------------------------------
__global__ void k_u1(P p) {
    float W[32], bb[4];
    #pragma unroll
    for (int k = 0; k < 32; k++) W[k] = __ldg(&p.uW1[k]);
    #pragma unroll
    for (int c = 0; c < 4; c++) bb[c] = __ldg(&p.ub1[c]);

    float s[4] = {0,0,0,0}, q[4] = {0,0,0,0};
    int stride = gridDim.x * blockDim.x;
    for (int n = blockIdx.x * blockDim.x + threadIdx.x; n < NN; n += stride) {
        float4 ag = g_aggr[n];
        float x[8] = { __ldg(&p.pos[2*n]), __ldg(&p.pos[2*n+1]),
                       __ldg(&p.vel[2*n]), __ldg(&p.vel[2*n+1]),
                       ag.x, ag.y, ag.z, ag.w };
        float z[4];
        #pragma unroll
        for (int c = 0; c < 4; c++) {
            float acc = bb[c];
            #pragma unroll
            for (int k = 0; k < 8; k++) acc += x[k] * W[k*4 + c];
            z[c] = acc;
            s[c] += acc; q[c] += acc*acc;
        }
        g_zu[n] = make_float4(z[0], z[1], z[2], z[3]);
    }
    reduce_stats(s, q);
    finalize_bn((double)NN, p.ug1, p.ube1, g_ua1, g_ub1);
}

// ---------------- K5: node update layer-2 stats ------------------------------
__global__ void k_u2(P p) {
    float a1[4], b1[4], W2[16], bb2[4];
    #pragma unroll
    for (int c = 0; c < 4; c++) { a1[c] = g_ua1[c]; b1[c] = g_ub1[c]; bb2[c] = __ldg(&p.ub2[c]); }
    #pragma unroll
    for (int k = 0; k < 16; k++) W2[k] = __ldg(&p.uW2[k]);

    float s[4] = {0,0,0,0}, q[4] = {0,0,0,0};
    int stride = gridDim.x * blockDim.x;
    for (int n = blockIdx.x * blockDim.x + threadIdx.x; n < NN; n += stride) {
        float4 zu = g_zu[n];
        float y[4];
        y[0] = fmaxf(0.f, zu.x * a1[0] + b1[0]);
        y[1] = fmaxf(0.f, zu.y * a1[1] + b1[1]);
        y[2] = fmaxf(0.f, zu.z * a1[2] + b1[2]);
        y[3] = fmaxf(0.f, zu.w * a1[3] + b1[3]);
        float z2[4];
        #pragma unroll
        for (int c = 0; c < 4; c++) {
            z2[c] = bb2[c] + y[0]*W2[c] + y[1]*W2[4+c] + y[2]*W2[8+c] + y[3]*W2[12+c];
            s[c] += z2[c]; q[c] += z2[c]*z2[c];
        }
        g_z2u[n] = make_float4(z2[0], z2[1], z2[2], z2[3]);
    }
    reduce_stats(s, q);
    finalize_bn((double)NN, p.ug2, p.ube2, g_ua2, g_ub2);
}

// ---------------- K6: final BN+ReLU + prediction head ------------------------
__global__ void k_out(P p) {
    float a2[4], b2[4], pW[8], pb[2];
    #pragma unroll
    for (int c = 0; c < 4; c++) { a2[c] = g_ua2[c]; b2[c] = g_ub2[c]; }
    #pragma unroll
    for (int k = 0; k < 8; k++) pW[k] = __ldg(&p.pW[k]);
    pb[0] = __ldg(&p.pb[0]); pb[1] = __ldg(&p.pb[1]);

    int stride = gridDim.x * blockDim.x;
    for (int n = blockIdx.x * blockDim.x + threadIdx.x; n < NN; n += stride) {
        float4 z2 = g_z2u[n];
        float u[4];
        u[0] = fmaxf(0.f, z2.x * a2[0] + b2[0]);
        u[1] = fmaxf(0.f, z2.y * a2[1] + b2[1]);
        u[2] = fmaxf(0.f, z2.z * a2[2] + b2[2]);
        u[3] = fmaxf(0.f, z2.w * a2[3] + b2[3]);
        float o0 = pb[0], o1 = pb[1];
        #pragma unroll
        for (int k = 0; k < 4; k++) { o0 += u[k] * pW[k*2]; o1 += u[k] * pW[k*2 + 1]; }
        p.out[2*n]   = o0;
        p.out[2*n+1] = o1;
    }
}

// ---------------- launch -----------------------------------------------------
extern "C" void kernel_launch(void* const* d_in, const int* in_sizes, int n_in,
                              void* d_out, int out_size) {
    P p;
    p.pos = (const float*)d_in[0];
    p.vel = (const float*)d_in[1];
    const int* ei = (const int*)d_in[2];   // int32 (JAX canonicalizes int64 -> int32)
    p.src = ei;            // edge_index[0]
    p.dst = ei + NE;       // edge_index[1]
    p.mW1  = (const float*)d_in[3];  p.mb1  = (const float*)d_in[4];
    p.mg1  = (const float*)d_in[5];  p.mbe1 = (const float*)d_in[6];
    p.mW2  = (const float*)d_in[7];  p.mb2  = (const float*)d_in[8];
    p.mg2  = (const float*)d_in[9];  p.mbe2 = (const float*)d_in[10];
    p.uW1  = (const float*)d_in[11]; p.ub1  = (const float*)d_in[12];
    p.ug1  = (const float*)d_in[13]; p.ube1 = (const float*)d_in[14];
    p.uW2  = (const float*)d_in[15]; p.ub2  = (const float*)d_in[16];
    p.ug2  = (const float*)d_in[17]; p.ube2 = (const float*)d_in[18];
    p.pW   = (const float*)d_in[19]; p.pb   = (const float*)d_in[20];
    p.out  = (float*)d_out;

    const int TB = 256;
    k_pre<<<(NN + TB - 1) / TB, TB>>>(p);
    k_e1 <<<1184, TB>>>(p);
    k_e2 <<<1184, TB>>>(p);
    k_e3 <<<1184, TB>>>(p);
    k_u1 <<<296,  TB>>>(p);
    k_u2 <<<296,  TB>>>(p);
    k_out<<<296,  TB>>>(p);
}

// round 3
// speedup vs baseline: 1.2094x; 1.2094x over previous
#include <cuda_runtime.h>
#include <cuda_bf16.h>

#define NN 100000
#define NE 6400000
static constexpr float BN_EPS = 1e-5f;

// ---------------- scratch (static device arrays; no runtime alloc) ---------
__device__ float4 g_A[NN];            // h @ msg_W1[0:4]   (dst-side partial)
__device__ float4 g_B[NN];            // h @ msg_W1[4:8]+b (src-side partial)
__device__ float4 g_z[NE];            // per-edge layer-1 pre-BN (102.4 MB)
__device__ float4 g_aggr[NN];         // scatter-add target
__device__ float4 g_zu[NN];           // node MLP layer-1 pre-BN
__device__ float4 g_z2u[NN];          // node MLP layer-2 pre-BN

__device__ double   g_sum[4];
__device__ double   g_sq[4];
__device__ unsigned g_cnt;

__device__ float g_ma1[4], g_mb1[4];  // msg BN1 affine (alpha, beta)
__device__ float g_ma2[4], g_mb2[4];  // msg BN2 affine
__device__ float g_ua1[4], g_ub1[4];  // upd BN1 affine
__device__ float g_ua2[4], g_ub2[4];  // upd BN2 affine

struct P {
    const float* pos; const float* vel;
    const int* src; const int* dst;   // edge_index rows (int32 after JAX x64 canonicalization)
    const float *mW1,*mb1,*mg1,*mbe1,*mW2,*mb2,*mg2,*mbe2;
    const float *uW1,*ub1,*ug1,*ube1,*uW2,*ub2,*ug2,*ube2;
    const float *pW,*pb;
    float* out;
};

// ---------------- reduction helpers ----------------------------------------
__device__ __forceinline__ void reduce_stats(float s[4], float q[4]) {
    #pragma unroll
    for (int o = 16; o > 0; o >>= 1) {
        #pragma unroll
        for (int c = 0; c < 4; c++) {
            s[c] += __shfl_down_sync(0xffffffffu, s[c], o);
            q[c] += __shfl_down_sync(0xffffffffu, q[c], o);
        }
    }
    __shared__ float shs[4][8], shq[4][8];
    int w = threadIdx.x >> 5;
    if ((threadIdx.x & 31) == 0) {
        #pragma unroll
        for (int c = 0; c < 4; c++) { shs[c][w] = s[c]; shq[c][w] = q[c]; }
    }
    __syncthreads();
    if (threadIdx.x == 0) {
        int nw = blockDim.x >> 5;
        #pragma unroll
        for (int c = 0; c < 4; c++) {
            double ts = 0.0, tq = 0.0;
            for (int i = 0; i < nw; i++) { ts += (double)shs[c][i]; tq += (double)shq[c][i]; }
            atomicAdd(&g_sum[c], ts);
            atomicAdd(&g_sq[c],  tq);
        }
    }
}

// last block through the counter folds the moments into BN affine params
__device__ __forceinline__ void finalize_bn(double count, const float* gamma, const float* beta,
                                            float* alpha_out, float* beta_out) {
    __threadfence();
    if (threadIdx.x == 0) {
        if (atomicAdd(&g_cnt, 1u) == gridDim.x - 1) {
            #pragma unroll
            for (int c = 0; c < 4; c++) {
                double m = ((volatile double*)g_sum)[c] / count;
                double v = ((volatile double*)g_sq)[c] / count - m * m;
                float  al = __ldg(&gamma[c]) * rsqrtf((float)v + BN_EPS);
                alpha_out[c] = al;
                beta_out[c]  = __ldg(&beta[c]) - (float)m * al;
                g_sum[c] = 0.0; g_sq[c] = 0.0;
            }
            g_cnt = 0u;
            __threadfence();
        }
    }
}

// ---------------- K0: per-node precompute + state reset --------------------
__global__ void k_pre(P p) {
    int n = blockIdx.x * blockDim.x + threadIdx.x;
    if (blockIdx.x == 0 && threadIdx.x == 0) {
        #pragma unroll
        for (int c = 0; c < 4; c++) { g_sum[c] = 0.0; g_sq[c] = 0.0; }
        g_cnt = 0u;
    }
    if (n >= NN) return;
    float h0 = __ldg(&p.pos[2*n]),  h1 = __ldg(&p.pos[2*n+1]);
    float h2 = __ldg(&p.vel[2*n]),  h3 = __ldg(&p.vel[2*n+1]);
    float A[4], B[4];
    #pragma unroll
    for (int c = 0; c < 4; c++) {
        A[c] = h0*__ldg(&p.mW1[ 0+c]) + h1*__ldg(&p.mW1[ 4+c])
             + h2*__ldg(&p.mW1[ 8+c]) + h3*__ldg(&p.mW1[12+c]);
        B[c] = __ldg(&p.mb1[c])
             + h0*__ldg(&p.mW1[16+c]) + h1*__ldg(&p.mW1[20+c])
             + h2*__ldg(&p.mW1[24+c]) + h3*__ldg(&p.mW1[28+c]);
    }
    g_A[n]    = make_float4(A[0], A[1], A[2], A[3]);
    g_B[n]    = make_float4(B[0], B[1], B[2], B[3]);
    g_aggr[n] = make_float4(0.f, 0.f, 0.f, 0.f);
}

// ---------------- K1: edge pass 1 — gather once, store z, layer-1 stats ----
__global__ void k_e1(P p) {
    float s[4] = {0,0,0,0}, q[4] = {0,0,0,0};
    int stride = gridDim.x * blockDim.x;
    for (int i = blockIdx.x * blockDim.x + threadIdx.x; i < NE; i += stride) {
        int si = __ldg(&p.src[i]);
        int di = __ldg(&p.dst[i]);
        float4 A = g_A[di], B = g_B[si];
        float4 z = make_float4(A.x + B.x, A.y + B.y, A.z + B.z, A.w + B.w);
        g_z[i] = z;
        s[0] += z.x; q[0] += z.x*z.x;
        s[1] += z.y; q[1] += z.y*z.y;
        s[2] += z.z; q[2] += z.z*z.z;
        s[3] += z.w; q[3] += z.w*z.w;
    }
    reduce_stats(s, q);
    finalize_bn((double)NE, p.mg1, p.mbe1, g_ma1, g_mb1);
}

// ---------------- K2: edge pass 2 — stream z, layer-2 stats -----------------
__global__ void k_e2(P p) {
    float a1[4], b1[4], W2[16], bb2[4];
    #pragma unroll
    for (int c = 0; c < 4; c++) { a1[c] = g_ma1[c]; b1[c] = g_mb1[c]; bb2[c] = __ldg(&p.mb2[c]); }
    #pragma unroll
    for (int k = 0; k < 16; k++) W2[k] = __ldg(&p.mW2[k]);

    float s[4] = {0,0,0,0}, q[4] = {0,0,0,0};
    int stride = gridDim.x * blockDim.x;
    for (int i = blockIdx.x * blockDim.x + threadIdx.x; i < NE; i += stride) {
        float4 z = g_z[i];
        float y[4];
        y[0] = fmaxf(0.f, z.x * a1[0] + b1[0]);
        y[1] = fmaxf(0.f, z.y * a1[1] + b1[1]);
        y[2] = fmaxf(0.f, z.z * a1[2] + b1[2]);
        y[3] = fmaxf(0.f, z.w * a1[3] + b1[3]);
        #pragma unroll
        for (int c = 0; c < 4; c++) {
            float z2 = bb2[c] + y[0]*W2[c] + y[1]*W2[4+c] + y[2]*W2[8+c] + y[3]*W2[12+c];
            s[c] += z2; q[c] += z2*z2;
        }
    }
    reduce_stats(s, q);
    finalize_bn((double)NE, p.mg2, p.mbe2, g_ma2, g_mb2);
}

// ---------------- K3: edge pass 3 — stream z + dst, message + scatter-add ---
__global__ void k_e3(P p) {
    float a1[4], b1[4], a2[4], b2a[4], W2[16], bb2[4];
    #pragma unroll
    for (int c = 0; c < 4; c++) {
        a1[c] = g_ma1[c]; b1[c] = g_mb1[c];
        a2[c] = g_ma2[c]; b2a[c] = g_mb2[c];
        bb2[c] = __ldg(&p.mb2[c]);
    }
    #pragma unroll
    for (int k = 0; k < 16; k++) W2[k] = __ldg(&p.mW2[k]);

    int stride = gridDim.x * blockDim.x;
    for (int i = blockIdx.x * blockDim.x + threadIdx.x; i < NE; i += stride) {
        int di = __ldg(&p.dst[i]);
        float4 z = g_z[i];
        float y[4];
        y[0] = fmaxf(0.f, z.x * a1[0] + b1[0]);
        y[1] = fmaxf(0.f, z.y * a1[1] + b1[1]);
        y[2] = fmaxf(0.f, z.z * a1[2] + b1[2]);
        y[3] = fmaxf(0.f, z.w * a1[3] + b1[3]);
        float m[4];
        #pragma unroll
        for (int c = 0; c < 4; c++) {
            float z2 = bb2[c] + y[0]*W2[c] + y[1]*W2[4+c] + y[2]*W2[8+c] + y[3]*W2[12+c];
            m[c] = fmaxf(0.f, z2 * a2[c] + b2a[c]);
        }
        float4* addr = &g_aggr[di];
        asm volatile("red.global.add.v4.f32 [%0], {%1, %2, %3, %4};"
                     :: "l"(addr), "f"(m[0]), "f"(m[1]), "f"(m[2]), "f"(m[3])
                     : "memory");
    }
}

// ---------------- K4: node update layer-1 stats ------------------------------
__global__ void k_u1(P p) {
    float W[32], bb[4];
    #pragma unroll
    for (int k = 0; k < 32; k++) W[k] = __ldg(&p.uW1[k]);
    #pragma unroll
    for (int c = 0; c < 4; c++) bb[c] = __ldg(&p.ub1[c]);

    float s[4] = {0,0,0,0}, q[4] = {0,0,0,0};
    int stride = gridDim.x * blockDim.x;
    for (int n = blockIdx.x * blockDim.x + threadIdx.x; n < NN; n += stride) {
        float4 ag = g_aggr[n];
        float x[8] = { __ldg(&p.pos[2*n]), __ldg(&p.pos[2*n+1]),
                       __ldg(&p.vel[2*n]), __ldg(&p.vel[2*n+1]),
                       ag.x, ag.y, ag.z, ag.w };
        float z[4];
        #pragma unroll
        for (int c = 0; c < 4; c++) {
            float acc = bb[c];
            #pragma unroll
            for (int k = 0; k < 8; k++) acc += x[k] * W[k*4 + c];
            z[c] = acc;
            s[c] += acc; q[c] += acc*acc;
        }
        g_zu[n] = make_float4(z[0], z[1], z[2], z[3]);
    }
    reduce_stats(s, q);
    finalize_bn((double)NN, p.ug1, p.ube1, g_ua1, g_ub1);
}

// ---------------- K5: node update layer-2 stats ------------------------------
__global__ void k_u2(P p) {
    float a1[4], b1[4], W2[16], bb2[4];
    #pragma unroll
    for (int c = 0; c < 4; c++) { a1[c] = g_ua1[c]; b1[c] = g_ub1[c]; bb2[c] = __ldg(&p.ub2[c]); }
    #pragma unroll
    for (int k = 0; k < 16; k++) W2[k] = __ldg(&p.uW2[k]);

    float s[4] = {0,0,0,0}, q[4] = {0,0,0,0};
    int stride = gridDim.x * blockDim.x;
    for (int n = blockIdx.x * blockDim.x + threadIdx.x; n < NN; n += stride) {
        float4 zu = g_zu[n];
        float y[4];
        y[0] = fmaxf(0.f, zu.x * a1[0] + b1[0]);
        y[1] = fmaxf(0.f, zu.y * a1[1] + b1[1]);
        y[2] = fmaxf(0.f, zu.z * a1[2] + b1[2]);
        y[3] = fmaxf(0.f, zu.w * a1[3] + b1[3]);
        float z2[4];
        #pragma unroll
        for (int c = 0; c < 4; c++) {
            z2[c] = bb2[c] + y[0]*W2[c] + y[1]*W2[4+c] + y[2]*W2[8+c] + y[3]*W2[12+c];
            s[c] += z2[c]; q[c] += z2[c]*z2[c];
        }
        g_z2u[n] = make_float4(z2[0], z2[1], z2[2], z2[3]);
    }
    reduce_stats(s, q);
    finalize_bn((double)NN, p.ug2, p.ube2, g_ua2, g_ub2);
}

// ---------------- K6: final BN+ReLU + prediction head ------------------------
__global__ void k_out(P p) {
    float a2[4], b2[4], pW[8], pb[2];
    #pragma unroll
    for (int c = 0; c < 4; c++) { a2[c] = g_ua2[c]; b2[c] = g_ub2[c]; }
    #pragma unroll
    for (int k = 0; k < 8; k++) pW[k] = __ldg(&p.pW[k]);
    pb[0] = __ldg(&p.pb[0]); pb[1] = __ldg(&p.pb[1]);

    int stride = gridDim.x * blockDim.x;
    for (int n = blockIdx.x * blockDim.x + threadIdx.x; n < NN; n += stride) {
        float4 z2 = g_z2u[n];
        float u[4];
        u[0] = fmaxf(0.f, z2.x * a2[0] + b2[0]);
        u[1] = fmaxf(0.f, z2.y * a2[1] + b2[1]);
        u[2] = fmaxf(0.f, z2.z * a2[2] + b2[2]);
        u[3] = fmaxf(0.f, z2.w * a2[3] + b2[3]);
        float o0 = pb[0], o1 = pb[1];
        #pragma unroll
        for (int k = 0; k < 4; k++) { o0 += u[k] * pW[k*2]; o1 += u[k] * pW[k*2 + 1]; }
        p.out[2*n]   = o0;
        p.out[2*n+1] = o1;
    }
}

// ---------------- launch -----------------------------------------------------
extern "C" void kernel_launch(void* const* d_in, const int* in_sizes, int n_in,
                              void* d_out, int out_size) {
    P p;
    p.pos = (const float*)d_in[0];
    p.vel = (const float*)d_in[1];
    const int* ei = (const int*)d_in[2];   // int32 (JAX canonicalizes int64 -> int32)
    p.src = ei;            // edge_index[0]
    p.dst = ei + NE;       // edge_index[1]
    p.mW1  = (const float*)d_in[3];  p.mb1  = (const float*)d_in[4];
    p.mg1  = (const float*)d_in[5];  p.mbe1 = (const float*)d_in[6];
    p.mW2  = (const float*)d_in[7];  p.mb2  = (const float*)d_in[8];
    p.mg2  = (const float*)d_in[9];  p.mbe2 = (const float*)d_in[10];
    p.uW1  = (const float*)d_in[11]; p.ub1  = (const float*)d_in[12];
    p.ug1  = (const float*)d_in[13]; p.ube1 = (const float*)d_in[14];
    p.uW2  = (const float*)d_in[15]; p.ub2  = (const float*)d_in[16];
    p.ug2  = (const float*)d_in[17]; p.ube2 = (const float*)d_in[18];
    p.pW   = (const float*)d_in[19]; p.pb   = (const float*)d_in[20];
    p.out  = (float*)d_out;

    const int TB = 256;
    k_pre<<<(NN + TB - 1) / TB, TB>>>(p);
    k_e1 <<<1184, TB>>>(p);
    k_e2 <<<1184, TB>>>(p);
    k_e3 <<<1184, TB>>>(p);
    k_u1 <<<296,  TB>>>(p);
    k_u2 <<<296,  TB>>>(p);
    k_out<<<296,  TB>>>(p);
}

// round 4
// speedup vs baseline: 1.3777x; 1.1391x over previous
#include <cuda_runtime.h>
#include <cuda_bf16.h>
#include <cuda_fp16.h>

#define NN 100000
#define NE 6400000
static constexpr float BN_EPS = 1e-5f;

// ---------------- scratch (static device arrays; no runtime alloc) ---------
__device__ float4 g_A[NN];            // h @ msg_W1[0:4]   (dst-side partial)
__device__ float4 g_B[NN];            // h @ msg_W1[4:8]+b (src-side partial)
__device__ uint2  g_z16[NE];          // per-edge layer-1 pre-BN, packed half4 (51.2 MB)
__device__ float4 g_aggr[NN];         // scatter-add target
__device__ float4 g_zu[NN];           // node MLP layer-1 pre-BN
__device__ float4 g_z2u[NN];          // node MLP layer-2 pre-BN

__device__ double   g_sum[4];
__device__ double   g_sq[4];
__device__ unsigned g_cnt;

__device__ float g_ma1[4], g_mb1[4];  // msg BN1 affine (alpha, beta)
__device__ float g_ma2[4], g_mb2[4];  // msg BN2 affine
__device__ float g_ua1[4], g_ub1[4];  // upd BN1 affine
__device__ float g_ua2[4], g_ub2[4];  // upd BN2 affine

struct P {
    const float* pos; const float* vel;
    const int* src; const int* dst;   // edge_index rows (int32)
    const float *mW1,*mb1,*mg1,*mbe1,*mW2,*mb2,*mg2,*mbe2;
    const float *uW1,*ub1,*ug1,*ube1,*uW2,*ub2,*ug2,*ube2;
    const float *pW,*pb;
    float* out;
};

// ---------------- half4 pack/unpack -----------------------------------------
__device__ __forceinline__ uint2 pack_half4(float x, float y, float z, float w) {
    __half2 a = __floats2half2_rn(x, y);
    __half2 b = __floats2half2_rn(z, w);
    uint2 u;
    u.x = *reinterpret_cast<unsigned*>(&a);
    u.y = *reinterpret_cast<unsigned*>(&b);
    return u;
}
__device__ __forceinline__ void unpack_half4(uint2 u, float z[4]) {
    __half2 a = *reinterpret_cast<__half2*>(&u.x);
    __half2 b = *reinterpret_cast<__half2*>(&u.y);
    float2 f0 = __half22float2(a), f1 = __half22float2(b);
    z[0] = f0.x; z[1] = f0.y; z[2] = f1.x; z[3] = f1.y;
}

// ---------------- reduction helpers ----------------------------------------
__device__ __forceinline__ void reduce_stats(float s[4], float q[4]) {
    #pragma unroll
    for (int o = 16; o > 0; o >>= 1) {
        #pragma unroll
        for (int c = 0; c < 4; c++) {
            s[c] += __shfl_down_sync(0xffffffffu, s[c], o);
            q[c] += __shfl_down_sync(0xffffffffu, q[c], o);
        }
    }
    __shared__ float shs[4][8], shq[4][8];
    int w = threadIdx.x >> 5;
    if ((threadIdx.x & 31) == 0) {
        #pragma unroll
        for (int c = 0; c < 4; c++) { shs[c][w] = s[c]; shq[c][w] = q[c]; }
    }
    __syncthreads();
    if (threadIdx.x == 0) {
        int nw = blockDim.x >> 5;
        #pragma unroll
        for (int c = 0; c < 4; c++) {
            double ts = 0.0, tq = 0.0;
            for (int i = 0; i < nw; i++) { ts += (double)shs[c][i]; tq += (double)shq[c][i]; }
            atomicAdd(&g_sum[c], ts);
            atomicAdd(&g_sq[c],  tq);
        }
    }
}

__device__ __forceinline__ void finalize_bn(double count, const float* gamma, const float* beta,
                                            float* alpha_out, float* beta_out) {
    __threadfence();
    if (threadIdx.x == 0) {
        if (atomicAdd(&g_cnt, 1u) == gridDim.x - 1) {
            #pragma unroll
            for (int c = 0; c < 4; c++) {
                double m = ((volatile double*)g_sum)[c] / count;
                double v = ((volatile double*)g_sq)[c] / count - m * m;
                float  al = __ldg(&gamma[c]) * rsqrtf((float)v + BN_EPS);
                alpha_out[c] = al;
                beta_out[c]  = __ldg(&beta[c]) - (float)m * al;
                g_sum[c] = 0.0; g_sq[c] = 0.0;
            }
            g_cnt = 0u;
            __threadfence();
        }
    }
}

// ---------------- K0: per-node precompute + state reset --------------------
__global__ void k_pre(P p) {
    int n = blockIdx.x * blockDim.x + threadIdx.x;
    if (blockIdx.x == 0 && threadIdx.x == 0) {
        #pragma unroll
        for (int c = 0; c < 4; c++) { g_sum[c] = 0.0; g_sq[c] = 0.0; }
        g_cnt = 0u;
    }
    if (n >= NN) return;
    float h0 = __ldg(&p.pos[2*n]),  h1 = __ldg(&p.pos[2*n+1]);
    float h2 = __ldg(&p.vel[2*n]),  h3 = __ldg(&p.vel[2*n+1]);
    float A[4], B[4];
    #pragma unroll
    for (int c = 0; c < 4; c++) {
        A[c] = h0*__ldg(&p.mW1[ 0+c]) + h1*__ldg(&p.mW1[ 4+c])
             + h2*__ldg(&p.mW1[ 8+c]) + h3*__ldg(&p.mW1[12+c]);
        B[c] = __ldg(&p.mb1[c])
             + h0*__ldg(&p.mW1[16+c]) + h1*__ldg(&p.mW1[20+c])
             + h2*__ldg(&p.mW1[24+c]) + h3*__ldg(&p.mW1[28+c]);
    }
    g_A[n]    = make_float4(A[0], A[1], A[2], A[3]);
    g_B[n]    = make_float4(B[0], B[1], B[2], B[3]);
    g_aggr[n] = make_float4(0.f, 0.f, 0.f, 0.f);
}

// ---------------- K1: edge pass 1 — gather, pack-store z, layer-1 stats ----
// 2 edges per thread per iteration: int2 index loads, uint4 z store.
__global__ void k_e1(P p) {
    float s[4] = {0,0,0,0}, q[4] = {0,0,0,0};
    const int2* src2 = (const int2*)p.src;
    const int2* dst2 = (const int2*)p.dst;
    uint4* z4 = (uint4*)g_z16;
    int stride = gridDim.x * blockDim.x;
    for (int j = blockIdx.x * blockDim.x + threadIdx.x; j < NE/2; j += stride) {
        int2 si = __ldg(&src2[j]);
        int2 di = __ldg(&dst2[j]);
        float4 A0 = g_A[di.x], B0 = g_B[si.x];
        float4 A1 = g_A[di.y], B1 = g_B[si.y];
        float z0[4] = {A0.x+B0.x, A0.y+B0.y, A0.z+B0.z, A0.w+B0.w};
        float z1[4] = {A1.x+B1.x, A1.y+B1.y, A1.z+B1.z, A1.w+B1.w};
        uint2 u0 = pack_half4(z0[0], z0[1], z0[2], z0[3]);
        uint2 u1 = pack_half4(z1[0], z1[1], z1[2], z1[3]);
        z4[j] = make_uint4(u0.x, u0.y, u1.x, u1.y);
        #pragma unroll
        for (int c = 0; c < 4; c++) {
            s[c] += z0[c] + z1[c];
            q[c] += z0[c]*z0[c] + z1[c]*z1[c];
        }
    }
    reduce_stats(s, q);
    finalize_bn((double)NE, p.mg1, p.mbe1, g_ma1, g_mb1);
}

// ---------------- K2: edge pass 2 — stream z (fp16), layer-2 stats ----------
__global__ void k_e2(P p) {
    float a1[4], b1[4], W2[16], bb2[4];
    #pragma unroll
    for (int c = 0; c < 4; c++) { a1[c] = g_ma1[c]; b1[c] = g_mb1[c]; bb2[c] = __ldg(&p.mb2[c]); }
    #pragma unroll
    for (int k = 0; k < 16; k++) W2[k] = __ldg(&p.mW2[k]);

    float s[4] = {0,0,0,0}, q[4] = {0,0,0,0};
    const uint4* z4 = (const uint4*)g_z16;
    int stride = gridDim.x * blockDim.x;
    for (int j = blockIdx.x * blockDim.x + threadIdx.x; j < NE/2; j += stride) {
        uint4 u = __ldg(&z4[j]);
        float z0[4], z1[4];
        unpack_half4(make_uint2(u.x, u.y), z0);
        unpack_half4(make_uint2(u.z, u.w), z1);
        #pragma unroll
        for (int e = 0; e < 2; e++) {
            const float* z = (e == 0) ? z0 : z1;
            float y[4];
            #pragma unroll
            for (int c = 0; c < 4; c++) y[c] = fmaxf(0.f, z[c] * a1[c] + b1[c]);
            #pragma unroll
            for (int c = 0; c < 4; c++) {
                float z2 = bb2[c] + y[0]*W2[c] + y[1]*W2[4+c] + y[2]*W2[8+c] + y[3]*W2[12+c];
                s[c] += z2; q[c] += z2*z2;
            }
        }
    }
    reduce_stats(s, q);
    finalize_bn((double)NE, p.mg2, p.mbe2, g_ma2, g_mb2);
}

// ---------------- K3: edge pass 3 — stream z + dst, message + scatter-add ---
__global__ void k_e3(P p) {
    float a1[4], b1[4], a2[4], b2a[4], W2[16], bb2[4];
    #pragma unroll
    for (int c = 0; c < 4; c++) {
        a1[c] = g_ma1[c]; b1[c] = g_mb1[c];
        a2[c] = g_ma2[c]; b2a[c] = g_mb2[c];
        bb2[c] = __ldg(&p.mb2[c]);
    }
    #pragma unroll
    for (int k = 0; k < 16; k++) W2[k] = __ldg(&p.mW2[k]);

    int stride = gridDim.x * blockDim.x;
    for (int i = blockIdx.x * blockDim.x + threadIdx.x; i < NE; i += stride) {
        int di = __ldg(&p.dst[i]);
        uint2 u = __ldg(&g_z16[i]);
        float z[4];
        unpack_half4(u, z);
        float y[4];
        #pragma unroll
        for (int c = 0; c < 4; c++) y[c] = fmaxf(0.f, z[c] * a1[c] + b1[c]);
        float m[4];
        #pragma unroll
        for (int c = 0; c < 4; c++) {
            float z2 = bb2[c] + y[0]*W2[c] + y[1]*W2[4+c] + y[2]*W2[8+c] + y[3]*W2[12+c];
            m[c] = fmaxf(0.f, z2 * a2[c] + b2a[c]);
        }
        float4* addr = &g_aggr[di];
        asm volatile("red.global.add.v4.f32 [%0], {%1, %2, %3, %4};"
                     :: "l"(addr), "f"(m[0]), "f"(m[1]), "f"(m[2]), "f"(m[3])
                     : "memory");
    }
}

// ---------------- K4: node update layer-1 stats ------------------------------
__global__ void k_u1(P p) {
    float W[32], bb[4];
    #pragma unroll
    for (int k = 0; k < 32; k++) W[k] = __ldg(&p.uW1[k]);
    #pragma unroll
    for (int c = 0; c < 4; c++) bb[c] = __ldg(&p.ub1[c]);

    float s[4] = {0,0,0,0}, q[4] = {0,0,0,0};
    int stride = gridDim.x * blockDim.x;
    for (int n = blockIdx.x * blockDim.x + threadIdx.x; n < NN; n += stride) {
        float4 ag = g_aggr[n];
        float x[8] = { __ldg(&p.pos[2*n]), __ldg(&p.pos[2*n+1]),
                       __ldg(&p.vel[2*n]), __ldg(&p.vel[2*n+1]),
                       ag.x, ag.y, ag.z, ag.w };
        float z[4];
        #pragma unroll
        for (int c = 0; c < 4; c++) {
            float acc = bb[c];
            #pragma unroll
            for (int k = 0; k < 8; k++) acc += x[k] * W[k*4 + c];
            z[c] = acc;
            s[c] += acc; q[c] += acc*acc;
        }
        g_zu[n] = make_float4(z[0], z[1], z[2], z[3]);
    }
    reduce_stats(s, q);
    finalize_bn((double)NN, p.ug1, p.ube1, g_ua1, g_ub1);
}

// ---------------- K5: node update layer-2 stats ------------------------------
__global__ void k_u2(P p) {
    float a1[4], b1[4], W2[16], bb2[4];
    #pragma unroll
    for (int c = 0; c < 4; c++) { a1[c] = g_ua1[c]; b1[c] = g_ub1[c]; bb2[c] = __ldg(&p.ub2[c]); }
    #pragma unroll
    for (int k = 0; k < 16; k++) W2[k] = __ldg(&p.uW2[k]);

    float s[4] = {0,0,0,0}, q[4] = {0,0,0,0};
    int stride = gridDim.x * blockDim.x;
    for (int n = blockIdx.x * blockDim.x + threadIdx.x; n < NN; n += stride) {
        float4 zu = g_zu[n];
        float y[4];
        y[0] = fmaxf(0.f, zu.x * a1[0] + b1[0]);
        y[1] = fmaxf(0.f, zu.y * a1[1] + b1[1]);
        y[2] = fmaxf(0.f, zu.z * a1[2] + b1[2]);
        y[3] = fmaxf(0.f, zu.w * a1[3] + b1[3]);
        float z2[4];
        #pragma unroll
        for (int c = 0; c < 4; c++) {
            z2[c] = bb2[c] + y[0]*W2[c] + y[1]*W2[4+c] + y[2]*W2[8+c] + y[3]*W2[12+c];
            s[c] += z2[c]; q[c] += z2[c]*z2[c];
        }
        g_z2u[n] = make_float4(z2[0], z2[1], z2[2], z2[3]);
    }
    reduce_stats(s, q);
    finalize_bn((double)NN, p.ug2, p.ube2, g_ua2, g_ub2);
}

// ---------------- K6: final BN+ReLU + prediction head ------------------------
__global__ void k_out(P p) {
    float a2[4], b2[4], pW[8], pb[2];
    #pragma unroll
    for (int c = 0; c < 4; c++) { a2[c] = g_ua2[c]; b2[c] = g_ub2[c]; }
    #pragma unroll
    for (int k = 0; k < 8; k++) pW[k] = __ldg(&p.pW[k]);
    pb[0] = __ldg(&p.pb[0]); pb[1] = __ldg(&p.pb[1]);

    int stride = gridDim.x * blockDim.x;
    for (int n = blockIdx.x * blockDim.x + threadIdx.x; n < NN; n += stride) {
        float4 z2 = g_z2u[n];
        float u[4];
        u[0] = fmaxf(0.f, z2.x * a2[0] + b2[0]);
        u[1] = fmaxf(0.f, z2.y * a2[1] + b2[1]);
        u[2] = fmaxf(0.f, z2.z * a2[2] + b2[2]);
        u[3] = fmaxf(0.f, z2.w * a2[3] + b2[3]);
        float o0 = pb[0], o1 = pb[1];
        #pragma unroll
        for (int k = 0; k < 4; k++) { o0 += u[k] * pW[k*2]; o1 += u[k] * pW[k*2 + 1]; }
        p.out[2*n]   = o0;
        p.out[2*n+1] = o1;
    }
}

// ---------------- launch -----------------------------------------------------
extern "C" void kernel_launch(void* const* d_in, const int* in_sizes, int n_in,
                              void* d_out, int out_size) {
    P p;
    p.pos = (const float*)d_in[0];
    p.vel = (const float*)d_in[1];
    const int* ei = (const int*)d_in[2];   // int32 (JAX canonicalizes int64 -> int32)
    p.src = ei;            // edge_index[0]
    p.dst = ei + NE;       // edge_index[1]
    p.mW1  = (const float*)d_in[3];  p.mb1  = (const float*)d_in[4];
    p.mg1  = (const float*)d_in[5];  p.mbe1 = (const float*)d_in[6];
    p.mW2  = (const float*)d_in[7];  p.mb2  = (const float*)d_in[8];
    p.mg2  = (const float*)d_in[9];  p.mbe2 = (const float*)d_in[10];
    p.uW1  = (const float*)d_in[11]; p.ub1  = (const float*)d_in[12];
    p.ug1  = (const float*)d_in[13]; p.ube1 = (const float*)d_in[14];
    p.uW2  = (const float*)d_in[15]; p.ub2  = (const float*)d_in[16];
    p.ug2  = (const float*)d_in[17]; p.ube2 = (const float*)d_in[18];
    p.pW   = (const float*)d_in[19]; p.pb   = (const float*)d_in[20];
    p.out  = (float*)d_out;

    const int TB = 256;
    k_pre<<<(NN + TB - 1) / TB, TB>>>(p);
    k_e1 <<<1184, TB>>>(p);
    k_e2 <<<1184, TB>>>(p);
    k_e3 <<<1184, TB>>>(p);
    k_u1 <<<296,  TB>>>(p);
    k_u2 <<<296,  TB>>>(p);
    k_out<<<296,  TB>>>(p);
}

// round 5
// speedup vs baseline: 1.5090x; 1.0954x over previous
#include <cuda_runtime.h>
#include <cuda_bf16.h>
#include <cuda_fp16.h>

#define NN 100000
#define NE 6400000
#define EGRID 592
#define ETB 256
#define ETHREADS (EGRID * ETB)   // 151552, = 148 SMs x 4 blocks
#define UGRID 296
#define UTB 256
#define UTHREADS (UGRID * UTB)   // 75776,  = 148 SMs x 2 blocks
static constexpr float BN_EPS = 1e-5f;

// ---------------- scratch (static device arrays; no runtime alloc) ---------
__device__ float4 g_A[NN];            // h @ msg_W1[0:4]   (dst-side partial)
__device__ float4 g_B[NN];            // h @ msg_W1[4:8]+b (src-side partial)
__device__ uint2  g_z16[NE];          // per-edge layer-1 pre-BN, packed half4 (51.2 MB)
__device__ float4 g_aggr[NN];         // scatter-add target

__device__ double g_sum[4];
__device__ double g_sq[4];

// grid-barrier state (monotonic counters; each kernel resets the OTHER's)
__device__ unsigned          g_ebar_cnt;
__device__ volatile unsigned g_ebar_rel;
__device__ unsigned          g_ubar_cnt;
__device__ volatile unsigned g_ubar_rel;

__device__ float g_ma1[4], g_mb1[4];  // msg BN1 affine
__device__ float g_ma2[4], g_mb2[4];  // msg BN2 affine
__device__ float g_ua1[4], g_ub1[4];  // upd BN1 affine
__device__ float g_ua2[4], g_ub2[4];  // upd BN2 affine

struct P {
    const float* pos; const float* vel;
    const int* src; const int* dst;   // edge_index rows (int32)
    const float *mW1,*mb1,*mg1,*mbe1,*mW2,*mb2,*mg2,*mbe2;
    const float *uW1,*ub1,*ug1,*ube1,*uW2,*ub2,*ug2,*ube2;
    const float *pW,*pb;
    float* out;
};

// ---------------- half4 pack/unpack -----------------------------------------
__device__ __forceinline__ uint2 pack_half4(float x, float y, float z, float w) {
    __half2 a = __floats2half2_rn(x, y);
    __half2 b = __floats2half2_rn(z, w);
    uint2 u;
    u.x = *reinterpret_cast<unsigned*>(&a);
    u.y = *reinterpret_cast<unsigned*>(&b);
    return u;
}
__device__ __forceinline__ void unpack_half4(unsigned lo, unsigned hi, float z[4]) {
    __half2 a = *reinterpret_cast<__half2*>(&lo);
    __half2 b = *reinterpret_cast<__half2*>(&hi);
    float2 f0 = __half22float2(a), f1 = __half22float2(b);
    z[0] = f0.x; z[1] = f0.y; z[2] = f1.x; z[3] = f1.y;
}

// ---------------- block-level stats reduce -> global atomics ----------------
__device__ __forceinline__ void reduce_stats(float s[4], float q[4]) {
    #pragma unroll
    for (int o = 16; o > 0; o >>= 1) {
        #pragma unroll
        for (int c = 0; c < 4; c++) {
            s[c] += __shfl_down_sync(0xffffffffu, s[c], o);
            q[c] += __shfl_down_sync(0xffffffffu, q[c], o);
        }
    }
    __shared__ float shs[4][8], shq[4][8];
    int w = threadIdx.x >> 5;
    if ((threadIdx.x & 31) == 0) {
        #pragma unroll
        for (int c = 0; c < 4; c++) { shs[c][w] = s[c]; shq[c][w] = q[c]; }
    }
    __syncthreads();
    if (threadIdx.x == 0) {
        int nw = blockDim.x >> 5;
        #pragma unroll
        for (int c = 0; c < 4; c++) {
            double ts = 0.0, tq = 0.0;
            for (int i = 0; i < nw; i++) { ts += (double)shs[c][i]; tq += (double)shq[c][i]; }
            atomicAdd(&g_sum[c], ts);
            atomicAdd(&g_sq[c],  tq);
        }
    }
}

// finalize BN affine from global moments (VOLATILE reads: L1 may hold stale
// lines from a previous finalize within this same launch; atomics only hit L2)
__device__ __forceinline__ void bn_finalize(double count, const float* gamma, const float* beta,
                                            float* aout, float* bout) {
    #pragma unroll
    for (int c = 0; c < 4; c++) {
        double m = ((volatile double*)g_sum)[c] / count;
        double v = ((volatile double*)g_sq)[c] / count - m * m;
        float  al = __ldg(&gamma[c]) * rsqrtf((float)v + BN_EPS);
        aout[c] = al;
        bout[c] = __ldg(&beta[c]) - (float)m * al;
        g_sum[c] = 0.0; g_sq[c] = 0.0;
    }
}

// grid-wide barrier; last arriver optionally runs the BN finalize before release.
// Requires ALL blocks of the grid co-resident (grid == exact SM capacity).
__device__ __forceinline__ void grid_barrier(unsigned* cnt, volatile unsigned* rel,
                                             int phase, int grid,
                                             double count = 0.0,
                                             const float* gamma = nullptr,
                                             const float* beta  = nullptr,
                                             float* aout = nullptr, float* bout = nullptr) {
    __threadfence();
    __syncthreads();
    if (threadIdx.x == 0) {
        unsigned old = atomicAdd(cnt, 1u);
        if (old == (unsigned)(phase * grid + grid - 1)) {
            if (gamma) bn_finalize(count, gamma, beta, aout, bout);
            __threadfence();
            *rel = (unsigned)(phase + 1);
        } else {
            while (*rel <= (unsigned)phase) __nanosleep(64);
        }
        __threadfence();
    }
    __syncthreads();
}

// ======================= fused edge kernel ==================================
// phase0: node precompute   -> barrier
// phase1: gather+store z, BN1 stats -> barrier(+fin BN1)
// phase2: stream z, BN2 stats       -> barrier(+fin BN2)
// phase3: stream z+dst, message, scatter-add
__global__ void __launch_bounds__(ETB, 4) k_edge(P p) {
    const int tid = blockIdx.x * ETB + threadIdx.x;

    // ---- phase 0: per-node precompute + state reset ----
    if (tid == 0) {
        g_ubar_cnt = 0; g_ubar_rel = 0;   // reset k_upd's barrier for this replay
        #pragma unroll
        for (int c = 0; c < 4; c++) { g_sum[c] = 0.0; g_sq[c] = 0.0; }
    }
    if (tid < NN) {
        float h0 = __ldg(&p.pos[2*tid]),  h1 = __ldg(&p.pos[2*tid+1]);
        float h2 = __ldg(&p.vel[2*tid]),  h3 = __ldg(&p.vel[2*tid+1]);
        float A[4], B[4];
        #pragma unroll
        for (int c = 0; c < 4; c++) {
            A[c] = h0*__ldg(&p.mW1[ 0+c]) + h1*__ldg(&p.mW1[ 4+c])
                 + h2*__ldg(&p.mW1[ 8+c]) + h3*__ldg(&p.mW1[12+c]);
            B[c] = __ldg(&p.mb1[c])
                 + h0*__ldg(&p.mW1[16+c]) + h1*__ldg(&p.mW1[20+c])
                 + h2*__ldg(&p.mW1[24+c]) + h3*__ldg(&p.mW1[28+c]);
        }
        g_A[tid]    = make_float4(A[0], A[1], A[2], A[3]);
        g_B[tid]    = make_float4(B[0], B[1], B[2], B[3]);
        g_aggr[tid] = make_float4(0.f, 0.f, 0.f, 0.f);
    }
    grid_barrier(&g_ebar_cnt, &g_ebar_rel, 0, EGRID);

    // ---- phase 1: gather once, pack-store z, layer-1 stats (2 edges/iter) ----
    {
        float s[4] = {0,0,0,0}, q[4] = {0,0,0,0};
        const int2* src2 = (const int2*)p.src;
        const int2* dst2 = (const int2*)p.dst;
        uint4* z4 = (uint4*)g_z16;
        for (int j = tid; j < NE/2; j += ETHREADS) {
            int2 si = __ldg(&src2[j]);
            int2 di = __ldg(&dst2[j]);
            float4 A0 = g_A[di.x], B0 = g_B[si.x];
            float4 A1 = g_A[di.y], B1 = g_B[si.y];
            float z0[4] = {A0.x+B0.x, A0.y+B0.y, A0.z+B0.z, A0.w+B0.w};
            float z1[4] = {A1.x+B1.x, A1.y+B1.y, A1.z+B1.z, A1.w+B1.w};
            uint2 u0 = pack_half4(z0[0], z0[1], z0[2], z0[3]);
            uint2 u1 = pack_half4(z1[0], z1[1], z1[2], z1[3]);
            z4[j] = make_uint4(u0.x, u0.y, u1.x, u1.y);
            #pragma unroll
            for (int c = 0; c < 4; c++) {
                s[c] += z0[c] + z1[c];
                q[c] += z0[c]*z0[c] + z1[c]*z1[c];
            }
        }
        reduce_stats(s, q);
    }
    grid_barrier(&g_ebar_cnt, &g_ebar_rel, 1, EGRID,
                 (double)NE, p.mg1, p.mbe1, g_ma1, g_mb1);

    // ---- phase 2: stream z, layer-2 stats (2 edges/iter) ----
    {
        float a1[4], b1[4], W2[16], bb2[4];
        #pragma unroll
        for (int c = 0; c < 4; c++) { a1[c] = g_ma1[c]; b1[c] = g_mb1[c]; bb2[c] = __ldg(&p.mb2[c]); }
        #pragma unroll
        for (int k = 0; k < 16; k++) W2[k] = __ldg(&p.mW2[k]);

        float s[4] = {0,0,0,0}, q[4] = {0,0,0,0};
        const uint4* z4 = (const uint4*)g_z16;
        for (int j = tid; j < NE/2; j += ETHREADS) {
            uint4 u = __ldg(&z4[j]);
            float z0[4], z1[4];
            unpack_half4(u.x, u.y, z0);
            unpack_half4(u.z, u.w, z1);
            #pragma unroll
            for (int e = 0; e < 2; e++) {
                const float* z = (e == 0) ? z0 : z1;
                float y[4];
                #pragma unroll
                for (int c = 0; c < 4; c++) y[c] = fmaxf(0.f, z[c] * a1[c] + b1[c]);
                #pragma unroll
                for (int c = 0; c < 4; c++) {
                    float z2 = bb2[c] + y[0]*W2[c] + y[1]*W2[4+c] + y[2]*W2[8+c] + y[3]*W2[12+c];
                    s[c] += z2; q[c] += z2*z2;
                }
            }
        }
        reduce_stats(s, q);
    }
    grid_barrier(&g_ebar_cnt, &g_ebar_rel, 2, EGRID,
                 (double)NE, p.mg2, p.mbe2, g_ma2, g_mb2);

    // ---- phase 3: stream z + dst, message, scatter-add (2 edges/iter) ----
    {
        float a1[4], b1[4], a2[4], b2a[4], W2[16], bb2[4];
        #pragma unroll
        for (int c = 0; c < 4; c++) {
            a1[c] = g_ma1[c]; b1[c] = g_mb1[c];
            a2[c] = g_ma2[c]; b2a[c] = g_mb2[c];
            bb2[c] = __ldg(&p.mb2[c]);
        }
        #pragma unroll
        for (int k = 0; k < 16; k++) W2[k] = __ldg(&p.mW2[k]);

        const int2* dst2 = (const int2*)p.dst;
        const uint4* z4 = (const uint4*)g_z16;
        for (int j = tid; j < NE/2; j += ETHREADS) {
            int2 di = __ldg(&dst2[j]);
            uint4 u = __ldg(&z4[j]);
            float z0[4], z1[4];
            unpack_half4(u.x, u.y, z0);
            unpack_half4(u.z, u.w, z1);
            float m0[4], m1[4];
            #pragma unroll
            for (int e = 0; e < 2; e++) {
                const float* z = (e == 0) ? z0 : z1;
                float* m = (e == 0) ? m0 : m1;
                float y[4];
                #pragma unroll
                for (int c = 0; c < 4; c++) y[c] = fmaxf(0.f, z[c] * a1[c] + b1[c]);
                #pragma unroll
                for (int c = 0; c < 4; c++) {
                    float z2 = bb2[c] + y[0]*W2[c] + y[1]*W2[4+c] + y[2]*W2[8+c] + y[3]*W2[12+c];
                    m[c] = fmaxf(0.f, z2 * a2[c] + b2a[c]);
                }
            }
            float4* a0 = &g_aggr[di.x];
            float4* a1p = &g_aggr[di.y];
            asm volatile("red.global.add.v4.f32 [%0], {%1, %2, %3, %4};"
                         :: "l"(a0), "f"(m0[0]), "f"(m0[1]), "f"(m0[2]), "f"(m0[3]) : "memory");
            asm volatile("red.global.add.v4.f32 [%0], {%1, %2, %3, %4};"
                         :: "l"(a1p), "f"(m1[0]), "f"(m1[1]), "f"(m1[2]), "f"(m1[3]) : "memory");
        }
    }
}

// ======================= fused node-update kernel ===========================
// Each thread owns up to 2 nodes; zu/z2 stay in registers across phases.
__global__ void __launch_bounds__(UTB, 2) k_upd(P p) {
    const int tid = blockIdx.x * UTB + threadIdx.x;
    if (tid == 0) { g_ebar_cnt = 0; g_ebar_rel = 0; }  // reset edge barrier for next replay

    const int n0 = tid, n1 = tid + UTHREADS;
    const bool v0 = (n0 < NN), v1 = (n1 < NN);

    float x0[8], x1[8];
    if (v0) {
        float2 ps = __ldg((const float2*)&p.pos[2*n0]);
        float2 vl = __ldg((const float2*)&p.vel[2*n0]);
        float4 ag = g_aggr[n0];
        x0[0]=ps.x; x0[1]=ps.y; x0[2]=vl.x; x0[3]=vl.y;
        x0[4]=ag.x; x0[5]=ag.y; x0[6]=ag.z; x0[7]=ag.w;
    }
    if (v1) {
        float2 ps = __ldg((const float2*)&p.pos[2*n1]);
        float2 vl = __ldg((const float2*)&p.vel[2*n1]);
        float4 ag = g_aggr[n1];
        x1[0]=ps.x; x1[1]=ps.y; x1[2]=vl.x; x1[3]=vl.y;
        x1[4]=ag.x; x1[5]=ag.y; x1[6]=ag.z; x1[7]=ag.w;
    }

    // ---- phase 0: layer-1 pre-BN (registers) + stats ----
    float zu0[4], zu1[4];
    {
        float W[32], bb[4];
        #pragma unroll
        for (int k = 0; k < 32; k++) W[k] = __ldg(&p.uW1[k]);
        #pragma unroll
        for (int c = 0; c < 4; c++) bb[c] = __ldg(&p.ub1[c]);

        float s[4] = {0,0,0,0}, q[4] = {0,0,0,0};
        if (v0) {
            #pragma unroll
            for (int c = 0; c < 4; c++) {
                float acc = bb[c];
                #pragma unroll
                for (int k = 0; k < 8; k++) acc += x0[k] * W[k*4 + c];
                zu0[c] = acc; s[c] += acc; q[c] += acc*acc;
            }
        }
        if (v1) {
            #pragma unroll
            for (int c = 0; c < 4; c++) {
                float acc = bb[c];
                #pragma unroll
                for (int k = 0; k < 8; k++) acc += x1[k] * W[k*4 + c];
                zu1[c] = acc; s[c] += acc; q[c] += acc*acc;
            }
        }
        reduce_stats(s, q);
    }
    grid_barrier(&g_ubar_cnt, &g_ubar_rel, 0, UGRID,
                 (double)NN, p.ug1, p.ube1, g_ua1, g_ub1);

    // ---- phase 1: layer-2 pre-BN (registers) + stats ----
    float z20[4], z21[4];
    {
        float a1[4], b1[4], W2[16], bb2[4];
        #pragma unroll
        for (int c = 0; c < 4; c++) { a1[c] = g_ua1[c]; b1[c] = g_ub1[c]; bb2[c] = __ldg(&p.ub2[c]); }
        #pragma unroll
        for (int k = 0; k < 16; k++) W2[k] = __ldg(&p.uW2[k]);

        float s[4] = {0,0,0,0}, q[4] = {0,0,0,0};
        if (v0) {
            float y[4];
            #pragma unroll
            for (int c = 0; c < 4; c++) y[c] = fmaxf(0.f, zu0[c] * a1[c] + b1[c]);
            #pragma unroll
            for (int c = 0; c < 4; c++) {
                z20[c] = bb2[c] + y[0]*W2[c] + y[1]*W2[4+c] + y[2]*W2[8+c] + y[3]*W2[12+c];
                s[c] += z20[c]; q[c] += z20[c]*z20[c];
            }
        }
        if (v1) {
            float y[4];
            #pragma unroll
            for (int c = 0; c < 4; c++) y[c] = fmaxf(0.f, zu1[c] * a1[c] + b1[c]);
            #pragma unroll
            for (int c = 0; c < 4; c++) {
                z21[c] = bb2[c] + y[0]*W2[c] + y[1]*W2[4+c] + y[2]*W2[8+c] + y[3]*W2[12+c];
                s[c] += z21[c]; q[c] += z21[c]*z21[c];
            }
        }
        reduce_stats(s, q);
    }
    grid_barrier(&g_ubar_cnt, &g_ubar_rel, 1, UGRID,
                 (double)NN, p.ug2, p.ube2, g_ua2, g_ub2);

    // ---- phase 2: final BN+ReLU + prediction head ----
    {
        float a2[4], b2[4], pW[8], pb0, pb1;
        #pragma unroll
        for (int c = 0; c < 4; c++) { a2[c] = g_ua2[c]; b2[c] = g_ub2[c]; }
        #pragma unroll
        for (int k = 0; k < 8; k++) pW[k] = __ldg(&p.pW[k]);
        pb0 = __ldg(&p.pb[0]); pb1 = __ldg(&p.pb[1]);

        if (v0) {
            float u[4];
            #pragma unroll
            for (int c = 0; c < 4; c++) u[c] = fmaxf(0.f, z20[c] * a2[c] + b2[c]);
            float o0 = pb0, o1 = pb1;
            #pragma unroll
            for (int k = 0; k < 4; k++) { o0 += u[k]*pW[k*2]; o1 += u[k]*pW[k*2+1]; }
            ((float2*)p.out)[n0] = make_float2(o0, o1);
        }
        if (v1) {
            float u[4];
            #pragma unroll
            for (int c = 0; c < 4; c++) u[c] = fmaxf(0.f, z21[c] * a2[c] + b2[c]);
            float o0 = pb0, o1 = pb1;
            #pragma unroll
            for (int k = 0; k < 4; k++) { o0 += u[k]*pW[k*2]; o1 += u[k]*pW[k*2+1]; }
            ((float2*)p.out)[n1] = make_float2(o0, o1);
        }
    }
}

// ---------------- launch -----------------------------------------------------
extern "C" void kernel_launch(void* const* d_in, const int* in_sizes, int n_in,
                              void* d_out, int out_size) {
    P p;
    p.pos = (const float*)d_in[0];
    p.vel = (const float*)d_in[1];
    const int* ei = (const int*)d_in[2];   // int32 (JAX canonicalizes int64 -> int32)
    p.src = ei;            // edge_index[0]
    p.dst = ei + NE;       // edge_index[1]
    p.mW1  = (const float*)d_in[3];  p.mb1  = (const float*)d_in[4];
    p.mg1  = (const float*)d_in[5];  p.mbe1 = (const float*)d_in[6];
    p.mW2  = (const float*)d_in[7];  p.mb2  = (const float*)d_in[8];
    p.mg2  = (const float*)d_in[9];  p.mbe2 = (const float*)d_in[10];
    p.uW1  = (const float*)d_in[11]; p.ub1  = (const float*)d_in[12];
    p.ug1  = (const float*)d_in[13]; p.ube1 = (const float*)d_in[14];
    p.uW2  = (const float*)d_in[15]; p.ub2  = (const float*)d_in[16];
    p.ug2  = (const float*)d_in[17]; p.ube2 = (const float*)d_in[18];
    p.pW   = (const float*)d_in[19]; p.pb   = (const float*)d_in[20];
    p.out  = (float*)d_out;

    k_edge<<<EGRID, ETB>>>(p);
    k_upd <<<UGRID, UTB>>>(p);
}